// round 13
// baseline (speedup 1.0000x reference)
#include <cuda_runtime.h>
#include <cuda_bf16.h>
#include <math_constants.h>
#include <math.h>

#define NTOT  8192
#define BHALF 4096
#define DDIM  128
#define KDIM  8192
#define NJS   4
#define LN2F  0.69314718055994531f

// ---------------- device scratch ----------------
__device__ __nv_bfloat16 g_h[NTOT * DDIM];        // concat(h_i,h_j) * sqrt(2*log2e)
__device__ __nv_bfloat16 g_axT[DDIM * KDIM];
__device__ float g_xs2[BHALF];
__device__ float g_ax2[KDIM];
__device__ float g_acc[4];                        // 1: t1, 2: t3, 3: t2
__device__ float g_lm[NJS * NTOT];
__device__ float g_ls[NJS * NTOT];
__device__ float g_lp[NJS * NTOT];

// ---------------- helpers ----------------
__device__ __forceinline__ void mma_bf16(float* c, const unsigned* a, unsigned b0, unsigned b1) {
    asm volatile(
        "mma.sync.aligned.m16n8k16.row.col.f32.bf16.bf16.f32 "
        "{%0,%1,%2,%3}, {%4,%5,%6,%7}, {%8,%9}, {%0,%1,%2,%3};\n"
        : "+f"(c[0]), "+f"(c[1]), "+f"(c[2]), "+f"(c[3])
        : "r"(a[0]), "r"(a[1]), "r"(a[2]), "r"(a[3]), "r"(b0), "r"(b1));
}
__device__ __forceinline__ unsigned pack_bf2(float x, float y) {
    __nv_bfloat162 b = __floats2bfloat162_rn(x, y);
    return *reinterpret_cast<unsigned*>(&b);
}
__device__ __forceinline__ void cp16(unsigned dst, const void* src) {
    asm volatile("cp.async.cg.shared.global [%0], [%1], 16;\n" :: "r"(dst), "l"(src));
}
__device__ __forceinline__ void cp_commit() { asm volatile("cp.async.commit_group;\n"); }
template<int N> __device__ __forceinline__ void cp_wait() {
    asm volatile("cp.async.wait_group %0;\n" :: "n"(N));
}
__device__ __forceinline__ void ldsm4(unsigned& r0, unsigned& r1, unsigned& r2, unsigned& r3,
                                      unsigned addr) {
    asm volatile("ldmatrix.sync.aligned.m8n8.x4.shared.b16 {%0,%1,%2,%3}, [%4];\n"
        : "=r"(r0), "=r"(r1), "=r"(r2), "=r"(r3) : "r"(addr));
}

// ---------------- prep ----------------
__global__ void __launch_bounds__(256) prep_kernel(const float* __restrict__ h_i,
                                                   const float* __restrict__ h_j,
                                                   const float* __restrict__ sub_x,
                                                   const float* __restrict__ all_x) {
    const float S = 1.69864360f;   // sqrt(2 * log2(e)); sim*2*log2e = (S*h_i)·(S*h_j)
    int tid = blockIdx.x * blockDim.x + threadIdx.x;
    int nth = gridDim.x * blockDim.x;

    int nh2 = NTOT * DDIM / 2;
    for (int idx = tid; idx < nh2; idx += nth) {
        int el  = idx << 1;
        int row = el >> 7;
        int col = el & 127;
        const float* src = (row < BHALF) ? (h_i + row * DDIM + col)
                                         : (h_j + (row - BHALF) * DDIM + col);
        float2 v = *reinterpret_cast<const float2*>(src);
        reinterpret_cast<__nv_bfloat162*>(g_h)[idx] = __floats2bfloat162_rn(v.x * S, v.y * S);
    }

    int wid = tid >> 5, lane = tid & 31, nw = nth >> 5;
    for (int r = wid; r < BHALF; r += nw) {
        float4 a = reinterpret_cast<const float4*>(sub_x + r * DDIM)[lane];
        float s = a.x*a.x + a.y*a.y + a.z*a.z + a.w*a.w;
        #pragma unroll
        for (int o = 16; o; o >>= 1) s += __shfl_xor_sync(0xffffffffu, s, o);
        if (lane == 0) g_xs2[r] = s;
    }
    for (int r = wid; r < KDIM; r += nw) {
        float4 a = reinterpret_cast<const float4*>(all_x + r * DDIM)[lane];
        float s = a.x*a.x + a.y*a.y + a.z*a.z + a.w*a.w;
        #pragma unroll
        for (int o = 16; o; o >>= 1) s += __shfl_xor_sync(0xffffffffu, s, o);
        if (lane == 0) g_ax2[r] = s;
    }

    if (blockIdx.x == 0 && tid < 4) g_acc[tid] = 0.f;
}

// ---------------- transpose all_x -> g_axT[d][k] ----------------
__global__ void __launch_bounds__(256) transpose_ax(const float* __restrict__ all_x) {
    __shared__ float t[32][33];
    int k0 = blockIdx.x * 32;
    int d0 = blockIdx.y * 32;
    int tx = threadIdx.x & 31, ty = threadIdx.x >> 5;
    #pragma unroll
    for (int j = 0; j < 4; j++) {
        int k = k0 + ty + j * 8;
        t[ty + j * 8][tx] = all_x[k * DDIM + d0 + tx];
    }
    __syncthreads();
    #pragma unroll
    for (int j = 0; j < 4; j++) {
        int d = d0 + ty + j * 8;
        g_axT[d * KDIM + k0 + tx] = __float2bfloat16(t[tx][ty + j * 8]);
    }
}

// ---------------- contrastive: 128-row CTA, warp 16x64, single-sync pipeline ----------------
#define CPAD 136
#define CNJT (NTOT / NJS / 64)   // 32 tiles per split

__global__ void __launch_bounds__(256, 2) contrastive_kernel() {
    __shared__ __nv_bfloat16 Bs[2][64 * CPAD];

    int tid = threadIdx.x;
    int warp = tid >> 5, lane = tid & 31;
    int g = lane >> 2, tig = lane & 3;
    int rb = blockIdx.x & 63;                   // 64 rowblocks of 128
    int js = blockIdx.x >> 6;                   // 0..3
    int jsBase = js * (NTOT / NJS);             // 2048-wide split
    int rowBlock = rb * 128;
    int r0 = warp * 16;                         // warp owns 16 rows, all 64 cols
    int rowG0 = rowBlock + r0 + g;
    int p0 = (rowG0 + BHALF) & (NTOT - 1);
    int p1 = (rowG0 + 8 + BHALF) & (NTOT - 1);

    // A fragments (32 regs), gmem direct — g_h is L2-resident (2MB)
    unsigned a_frag[8][4];
    #pragma unroll
    for (int ks = 0; ks < 8; ks++) {
        int kc = ks * 16 + tig * 2;
        a_frag[ks][0] = *reinterpret_cast<const unsigned*>(g_h + rowG0 * DDIM + kc);
        a_frag[ks][1] = *reinterpret_cast<const unsigned*>(g_h + (rowG0 + 8) * DDIM + kc);
        a_frag[ks][2] = *reinterpret_cast<const unsigned*>(g_h + rowG0 * DDIM + kc + 8);
        a_frag[ks][3] = *reinterpret_cast<const unsigned*>(g_h + (rowG0 + 8) * DDIM + kc + 8);
    }

    unsigned bsh[2];
    bsh[0] = (unsigned)__cvta_generic_to_shared(&Bs[0][0]);
    bsh[1] = (unsigned)__cvta_generic_to_shared(&Bs[1][0]);

    // ldmatrix lane addressing (verified layout from R11): matrix idx = n-tile, row = col j
    unsigned rowoffA = (unsigned)((((lane >> 3) * 8) + (lane & 7)) * CPAD * 2);
    unsigned rowoffB = rowoffA + 32u * CPAD * 2;

    // prefetch tile 0
    #pragma unroll
    for (int j = 0; j < 4; j++) {
        int i = tid + j * 256;
        int r = i >> 4, c8 = i & 15;
        cp16(bsh[0] + (r * CPAD + c8 * 8) * 2, g_h + (jsBase + r) * DDIM + c8 * 8);
    }
    cp_commit();

    float m0r = -CUDART_INF_F, m1r = -CUDART_INF_F;
    float s0r = 0.f, s1r = 0.f;
    float pos0 = -CUDART_INF_F, pos1 = -CUDART_INF_F;

    for (int ct = 0; ct < CNJT; ct++) {
        int cur = ct & 1;
        cp_wait<0>();          // tile ct arrived (this thread's copies)
        __syncthreads();       // visible to all; all threads done with buf cur^1
        if (ct + 1 < CNJT) {   // overwrite buf cur^1 (tile ct-1, consumed) with tile ct+1
            #pragma unroll
            for (int j = 0; j < 4; j++) {
                int i = tid + j * 256;
                int r = i >> 4, c8 = i & 15;
                cp16(bsh[cur ^ 1] + (r * CPAD + c8 * 8) * 2,
                     g_h + (jsBase + (ct + 1) * 64 + r) * DDIM + c8 * 8);
            }
            cp_commit();
        }

        float acc[8][4];
        #pragma unroll
        for (int nt = 0; nt < 8; nt++)
            acc[nt][0] = acc[nt][1] = acc[nt][2] = acc[nt][3] = 0.f;

        #pragma unroll
        for (int ks = 0; ks < 8; ks++) {
            unsigned b0[8], b1[8];
            ldsm4(b0[0], b0[1], b0[2], b0[3], bsh[cur] + rowoffA + ks * 32);
            ldsm4(b0[4], b0[5], b0[6], b0[7], bsh[cur] + rowoffB + ks * 32);
            ldsm4(b1[0], b1[1], b1[2], b1[3], bsh[cur] + rowoffA + ks * 32 + 16);
            ldsm4(b1[4], b1[5], b1[6], b1[7], bsh[cur] + rowoffB + ks * 32 + 16);
            #pragma unroll
            for (int nt = 0; nt < 8; nt++)
                mma_bf16(acc[nt], a_frag[ks], b0[nt], b1[nt]);
        }

        // epilogue, log2-domain (values already scaled by 2*log2e), no vv spill:
        int jbase = jsBase + ct * 64 + tig * 2;
        // pass 1: max + positive capture
        float tm0 = -CUDART_INF_F, tm1 = -CUDART_INF_F;
        #pragma unroll
        for (int nt = 0; nt < 8; nt++) {
            #pragma unroll
            for (int q = 0; q < 2; q++) {
                int jc = jbase + nt * 8 + q;
                float x0 = acc[nt][q];
                float x1 = acc[nt][2 + q];
                if (jc == p0) pos0 = x0;
                if (jc == p1) pos1 = x1;
                if (jc != rowG0)     tm0 = fmaxf(tm0, x0);
                if (jc != rowG0 + 8) tm1 = fmaxf(tm1, x1);
            }
        }
        float nm0 = fmaxf(m0r, tm0), nm1 = fmaxf(m1r, tm1);
        float a0 = s0r * exp2f(m0r - nm0);
        float a1 = s1r * exp2f(m1r - nm1);
        // pass 2: sum of exp2 (masked diag -> exp2(-inf) = 0)
        #pragma unroll
        for (int nt = 0; nt < 8; nt++) {
            #pragma unroll
            for (int q = 0; q < 2; q++) {
                int jc = jbase + nt * 8 + q;
                float x0 = (jc == rowG0)     ? -CUDART_INF_F : acc[nt][q];
                float x1 = (jc == rowG0 + 8) ? -CUDART_INF_F : acc[nt][2 + q];
                a0 += exp2f(x0 - nm0);
                a1 += exp2f(x1 - nm1);
            }
        }
        m0r = nm0; s0r = a0; m1r = nm1; s1r = a1;
    }

    // merge across tig (offsets 1,2)
    #pragma unroll
    for (int o = 1; o <= 2; o <<= 1) {
        float mo = __shfl_xor_sync(0xffffffffu, m0r, o);
        float so = __shfl_xor_sync(0xffffffffu, s0r, o);
        float nm = fmaxf(m0r, mo);
        s0r = s0r * exp2f(m0r - nm) + so * exp2f(mo - nm); m0r = nm;
        mo = __shfl_xor_sync(0xffffffffu, m1r, o);
        so = __shfl_xor_sync(0xffffffffu, s1r, o);
        nm = fmaxf(m1r, mo);
        s1r = s1r * exp2f(m1r - nm) + so * exp2f(mo - nm); m1r = nm;
        pos0 = fmaxf(pos0, __shfl_xor_sync(0xffffffffu, pos0, o));
        pos1 = fmaxf(pos1, __shfl_xor_sync(0xffffffffu, pos1, o));
    }
    if (tig == 0) {   // one col-warp per tile: no cross-warp merge needed
        int row = js * NTOT + rowBlock + r0 + g;
        g_lm[row] = m0r; g_ls[row] = s0r; g_lp[row] = pos0;
        g_lm[row + 8] = m1r; g_ls[row + 8] = s1r; g_lp[row + 8] = pos1;
    }
}

// ---------------- graph: R10 structure + single-sync pipeline ----------------
#define KPX 40
#define GKSPLIT 8
#define GKS (KDIM / GKSPLIT)   // 1024

__global__ void __launch_bounds__(256, 2) graph_kernel(const float* __restrict__ G,
                                                       const float* __restrict__ sub_x) {
    __shared__ __nv_bfloat16 Xs[2][128 * KPX];

    int tid = threadIdx.x;
    int warp = tid >> 5, lane = tid & 31;
    int g = lane >> 2, tig = lane & 3;
    int rb  = blockIdx.x & 31;
    int ksp = blockIdx.x >> 5;
    int rowBase = rb * 128;
    int kBase   = ksp * GKS;

    float acc[16][4];
    #pragma unroll
    for (int nt = 0; nt < 16; nt++)
        acc[nt][0] = acc[nt][1] = acc[nt][2] = acc[nt][3] = 0.f;
    float rsum0 = 0.f, rsum1 = 0.f, t2p = 0.f;

    int r0 = warp * 16;
    int rowA = rowBase + r0 + g;
    int rowB = rowA + 8;
    const float* gRowA = G + (size_t)rowA * KDIM + kBase + tig * 2;
    const float* gRowB = G + (size_t)rowB * KDIM + kBase + tig * 2;
    const float* axp   = g_ax2 + kBase + tig * 2;

    unsigned xsh[2];
    xsh[0] = (unsigned)__cvta_generic_to_shared(&Xs[0][0]);
    xsh[1] = (unsigned)__cvta_generic_to_shared(&Xs[1][0]);

    #pragma unroll
    for (int j = 0; j < 2; j++) {
        int i = tid + j * 256;
        int d = i >> 2, q = i & 3;
        cp16(xsh[0] + (d * KPX + q * 8) * 2, g_axT + d * KDIM + kBase + q * 8);
    }
    cp_commit();

    float2 bA0 = *reinterpret_cast<const float2*>(gRowA);
    float2 bB0 = *reinterpret_cast<const float2*>(gRowB);
    float2 bA1 = *reinterpret_cast<const float2*>(gRowA + 8);
    float2 bB1 = *reinterpret_cast<const float2*>(gRowB + 8);

    for (int kt = 0; kt < GKS / 32; kt++) {
        int cur = kt & 1;
        cp_wait<0>();
        __syncthreads();       // tile kt visible; all threads done with buf cur^1
        if (kt + 1 < GKS / 32) {
            #pragma unroll
            for (int j = 0; j < 2; j++) {
                int i = tid + j * 256;
                int d = i >> 2, q = i & 3;
                cp16(xsh[cur ^ 1] + (d * KPX + q * 8) * 2,
                     g_axT + d * KDIM + kBase + (kt + 1) * 32 + q * 8);
            }
            cp_commit();
        }

        #pragma unroll
        for (int ks = 0; ks < 2; ks++) {
            int kk = kt * 2 + ks;
            float2 vA0 = bA0, vB0 = bB0, vA1 = bA1, vB1 = bB1;
            int ncol = (kk + 1 < GKS / 16) ? (kk + 1) * 16 : 0;
            bA0 = *reinterpret_cast<const float2*>(gRowA + ncol);
            bB0 = *reinterpret_cast<const float2*>(gRowB + ncol);
            bA1 = *reinterpret_cast<const float2*>(gRowA + ncol + 8);
            bB1 = *reinterpret_cast<const float2*>(gRowB + ncol + 8);

            rsum0 += vA0.x + vA0.y + vA1.x + vA1.y;
            rsum1 += vB0.x + vB0.y + vB1.x + vB1.y;

            float2 w0 = *reinterpret_cast<const float2*>(axp + kk * 16);
            float2 w1 = *reinterpret_cast<const float2*>(axp + kk * 16 + 8);
            t2p += (vA0.x + vB0.x) * w0.x + (vA0.y + vB0.y) * w0.y
                 + (vA1.x + vB1.x) * w1.x + (vA1.y + vB1.y) * w1.y;

            unsigned af[4];
            af[0] = pack_bf2(vA0.x, vA0.y);
            af[1] = pack_bf2(vB0.x, vB0.y);
            af[2] = pack_bf2(vA1.x, vA1.y);
            af[3] = pack_bf2(vB1.x, vB1.y);
            #pragma unroll
            for (int nt = 0; nt < 16; nt++) {
                const __nv_bfloat16* bp = &Xs[cur][(nt * 8 + g) * KPX + ks * 16 + tig * 2];
                unsigned b0 = *reinterpret_cast<const unsigned*>(bp);
                unsigned b1 = *reinterpret_cast<const unsigned*>(bp + 8);
                mma_bf16(acc[nt], af, b0, b1);
            }
        }
    }

    // t3 partial
    float t3p = 0.f;
    #pragma unroll
    for (int nt = 0; nt < 16; nt++) {
        int d = nt * 8 + tig * 2;
        float2 s0 = *reinterpret_cast<const float2*>(sub_x + rowA * DDIM + d);
        float2 s1 = *reinterpret_cast<const float2*>(sub_x + rowB * DDIM + d);
        t3p += acc[nt][0] * s0.x + acc[nt][1] * s0.y + acc[nt][2] * s1.x + acc[nt][3] * s1.y;
    }
    #pragma unroll
    for (int o = 16; o; o >>= 1) t3p += __shfl_xor_sync(0xffffffffu, t3p, o);
    if (lane == 0) atomicAdd(&g_acc[2], t3p);

    // t2 partial
    #pragma unroll
    for (int o = 16; o; o >>= 1) t2p += __shfl_xor_sync(0xffffffffu, t2p, o);
    if (lane == 0) atomicAdd(&g_acc[3], t2p);

    // t1 partial
    rsum0 += __shfl_xor_sync(0xffffffffu, rsum0, 1);
    rsum0 += __shfl_xor_sync(0xffffffffu, rsum0, 2);
    rsum1 += __shfl_xor_sync(0xffffffffu, rsum1, 1);
    rsum1 += __shfl_xor_sync(0xffffffffu, rsum1, 2);
    float t1p = 0.f;
    if (tig == 0) t1p = rsum0 * g_xs2[rowA] + rsum1 * g_xs2[rowB];
    #pragma unroll
    for (int o = 4; o <= 16; o <<= 1) t1p += __shfl_xor_sync(0xffffffffu, t1p, o);
    if (lane == 0) atomicAdd(&g_acc[1], t1p);
}

// ---------------- finalize: log2-domain LSE merge + combine ----------------
__global__ void __launch_bounds__(256) finalize_kernel(float* __restrict__ out) {
    __shared__ float red[8];
    int tid = threadIdx.x;
    float csum = 0.f;
    for (int r = tid; r < NTOT; r += 256) {
        float m = g_lm[r], s = g_ls[r], p = g_lp[r];
        #pragma unroll
        for (int js = 1; js < NJS; js++) {
            float mo = g_lm[js * NTOT + r], so = g_ls[js * NTOT + r];
            float nm = fmaxf(m, mo);
            s = s * exp2f(m - nm) + so * exp2f(mo - nm);
            m = nm;
            p = fmaxf(p, g_lp[js * NTOT + r]);
        }
        csum += LN2F * (m + log2f(s) - p);
    }
    #pragma unroll
    for (int o = 16; o; o >>= 1) csum += __shfl_xor_sync(0xffffffffu, csum, o);
    if ((tid & 31) == 0) red[tid >> 5] = csum;
    __syncthreads();
    if (tid == 0) {
        float cs = 0.f;
        #pragma unroll
        for (int i = 0; i < 8; i++) cs += red[i];
        float contr = cs / (float)NTOT;
        float graph = (g_acc[1] + g_acc[3] - 2.0f * g_acc[2]) / ((float)BHALF * (float)KDIM);
        out[0] = contr + graph;
    }
}

// ---------------- launch ----------------
extern "C" void kernel_launch(void* const* d_in, const int* in_sizes, int n_in,
                              void* d_out, int out_size) {
    (void)in_sizes; (void)n_in; (void)out_size;
    const float* h_i   = (const float*)d_in[0];
    const float* h_j   = (const float*)d_in[1];
    const float* G     = (const float*)d_in[2];
    const float* sub_x = (const float*)d_in[3];
    const float* all_x = (const float*)d_in[4];
    float* out = (float*)d_out;

    prep_kernel<<<512, 256>>>(h_i, h_j, sub_x, all_x);
    transpose_ax<<<dim3(256, 4), 256>>>(all_x);
    contrastive_kernel<<<256, 256>>>();
    graph_kernel<<<256, 256>>>(G, sub_x);
    finalize_kernel<<<1, 256>>>(out);
}

// round 14
// speedup vs baseline: 1.0917x; 1.0917x over previous
#include <cuda_runtime.h>
#include <cuda_bf16.h>
#include <math_constants.h>
#include <math.h>

#define NTOT  8192
#define BHALF 4096
#define DDIM  128
#define KDIM  8192
#define NJS   4
#define LN2F  0.69314718055994531f

// ---------------- device scratch ----------------
__device__ __nv_bfloat16 g_h[NTOT * DDIM];        // concat(h_i,h_j) * sqrt(2*log2e)
__device__ __nv_bfloat16 g_axT[DDIM * KDIM];
__device__ float g_xs2[BHALF];
__device__ float g_ax2[KDIM];
__device__ float g_acc[4];                        // 1: t1, 2: t3, 3: t2
__device__ float g_lm[NJS * NTOT];
__device__ float g_ls[NJS * NTOT];
__device__ float g_lp[NJS * NTOT];

// ---------------- helpers ----------------
__device__ __forceinline__ void mma_bf16(float* c, const unsigned* a, unsigned b0, unsigned b1) {
    asm volatile(
        "mma.sync.aligned.m16n8k16.row.col.f32.bf16.bf16.f32 "
        "{%0,%1,%2,%3}, {%4,%5,%6,%7}, {%8,%9}, {%0,%1,%2,%3};\n"
        : "+f"(c[0]), "+f"(c[1]), "+f"(c[2]), "+f"(c[3])
        : "r"(a[0]), "r"(a[1]), "r"(a[2]), "r"(a[3]), "r"(b0), "r"(b1));
}
__device__ __forceinline__ unsigned pack_bf2(float x, float y) {
    __nv_bfloat162 b = __floats2bfloat162_rn(x, y);
    return *reinterpret_cast<unsigned*>(&b);
}
__device__ __forceinline__ void cp16(unsigned dst, const void* src) {
    asm volatile("cp.async.cg.shared.global [%0], [%1], 16;\n" :: "r"(dst), "l"(src));
}
__device__ __forceinline__ void cp_commit() { asm volatile("cp.async.commit_group;\n"); }
template<int N> __device__ __forceinline__ void cp_wait() {
    asm volatile("cp.async.wait_group %0;\n" :: "n"(N));
}
__device__ __forceinline__ void ldsm4(unsigned& r0, unsigned& r1, unsigned& r2, unsigned& r3,
                                      unsigned addr) {
    asm volatile("ldmatrix.sync.aligned.m8n8.x4.shared.b16 {%0,%1,%2,%3}, [%4];\n"
        : "=r"(r0), "=r"(r1), "=r"(r2), "=r"(r3) : "r"(addr));
}

// ---------------- prep ----------------
__global__ void __launch_bounds__(256) prep_kernel(const float* __restrict__ h_i,
                                                   const float* __restrict__ h_j,
                                                   const float* __restrict__ sub_x,
                                                   const float* __restrict__ all_x) {
    const float S = 1.69864360f;   // sqrt(2 * log2(e))
    int tid = blockIdx.x * blockDim.x + threadIdx.x;
    int nth = gridDim.x * blockDim.x;

    int nh2 = NTOT * DDIM / 2;
    for (int idx = tid; idx < nh2; idx += nth) {
        int el  = idx << 1;
        int row = el >> 7;
        int col = el & 127;
        const float* src = (row < BHALF) ? (h_i + row * DDIM + col)
                                         : (h_j + (row - BHALF) * DDIM + col);
        float2 v = *reinterpret_cast<const float2*>(src);
        reinterpret_cast<__nv_bfloat162*>(g_h)[idx] = __floats2bfloat162_rn(v.x * S, v.y * S);
    }

    int wid = tid >> 5, lane = tid & 31, nw = nth >> 5;
    for (int r = wid; r < BHALF; r += nw) {
        float4 a = reinterpret_cast<const float4*>(sub_x + r * DDIM)[lane];
        float s = a.x*a.x + a.y*a.y + a.z*a.z + a.w*a.w;
        #pragma unroll
        for (int o = 16; o; o >>= 1) s += __shfl_xor_sync(0xffffffffu, s, o);
        if (lane == 0) g_xs2[r] = s;
    }
    for (int r = wid; r < KDIM; r += nw) {
        float4 a = reinterpret_cast<const float4*>(all_x + r * DDIM)[lane];
        float s = a.x*a.x + a.y*a.y + a.z*a.z + a.w*a.w;
        #pragma unroll
        for (int o = 16; o; o >>= 1) s += __shfl_xor_sync(0xffffffffu, s, o);
        if (lane == 0) g_ax2[r] = s;
    }

    if (blockIdx.x == 0 && tid < 4) g_acc[tid] = 0.f;
}

// ---------------- transpose all_x -> g_axT[d][k] ----------------
__global__ void __launch_bounds__(256) transpose_ax(const float* __restrict__ all_x) {
    __shared__ float t[32][33];
    int k0 = blockIdx.x * 32;
    int d0 = blockIdx.y * 32;
    int tx = threadIdx.x & 31, ty = threadIdx.x >> 5;
    #pragma unroll
    for (int j = 0; j < 4; j++) {
        int k = k0 + ty + j * 8;
        t[ty + j * 8][tx] = all_x[k * DDIM + d0 + tx];
    }
    __syncthreads();
    #pragma unroll
    for (int j = 0; j < 4; j++) {
        int d = d0 + ty + j * 8;
        g_axT[d * KDIM + k0 + tx] = __float2bfloat16(t[tx][ty + j * 8]);
    }
}

// ---------------- contrastive: 128-row CTA, warp 16x64, fast/slow epilogue ----------------
#define CPAD 136
#define CNJT (NTOT / NJS / 64)   // 32 tiles per split

__global__ void __launch_bounds__(256, 2) contrastive_kernel() {
    __shared__ __nv_bfloat16 Bs[2][64 * CPAD];

    int tid = threadIdx.x;
    int warp = tid >> 5, lane = tid & 31;
    int g = lane >> 2, tig = lane & 3;
    int rb = blockIdx.x & 63;
    int js = blockIdx.x >> 6;                   // 0..3
    int jsBase = js * (NTOT / NJS);
    int rowBlock = rb * 128;
    int r0 = warp * 16;
    int rowG0 = rowBlock + r0 + g;
    int p0 = (rowG0 + BHALF) & (NTOT - 1);
    int p1 = (rowG0 + 8 + BHALF) & (NTOT - 1);

    // warp-uniform special tiles (16-row bands are 64-tile aligned, never straddle)
    int bandBase = rowBlock + r0;
    int pBand = (bandBase + BHALF) & (NTOT - 1);
    bool dIn = ((unsigned)(bandBase - jsBase)) < (unsigned)(NTOT / NJS);
    bool pIn = ((unsigned)(pBand - jsBase))    < (unsigned)(NTOT / NJS);
    int diagTile = dIn ? ((bandBase - jsBase) >> 6) : -1;
    int posTile  = pIn ? ((pBand - jsBase) >> 6)    : -2;

    // A fragments (32 regs), gmem direct — g_h is L2-resident
    unsigned a_frag[8][4];
    #pragma unroll
    for (int ks = 0; ks < 8; ks++) {
        int kc = ks * 16 + tig * 2;
        a_frag[ks][0] = *reinterpret_cast<const unsigned*>(g_h + rowG0 * DDIM + kc);
        a_frag[ks][1] = *reinterpret_cast<const unsigned*>(g_h + (rowG0 + 8) * DDIM + kc);
        a_frag[ks][2] = *reinterpret_cast<const unsigned*>(g_h + rowG0 * DDIM + kc + 8);
        a_frag[ks][3] = *reinterpret_cast<const unsigned*>(g_h + (rowG0 + 8) * DDIM + kc + 8);
    }

    unsigned bsh[2];
    bsh[0] = (unsigned)__cvta_generic_to_shared(&Bs[0][0]);
    bsh[1] = (unsigned)__cvta_generic_to_shared(&Bs[1][0]);

    unsigned rowoffA = (unsigned)((((lane >> 3) * 8) + (lane & 7)) * CPAD * 2);
    unsigned rowoffB = rowoffA + 32u * CPAD * 2;

    // prefetch tile 0
    #pragma unroll
    for (int j = 0; j < 4; j++) {
        int i = tid + j * 256;
        int r = i >> 4, c8 = i & 15;
        cp16(bsh[0] + (r * CPAD + c8 * 8) * 2, g_h + (jsBase + r) * DDIM + c8 * 8);
    }
    cp_commit();

    float m0r = -CUDART_INF_F, m1r = -CUDART_INF_F;
    float s0r = 0.f, s1r = 0.f;
    float pos0 = -CUDART_INF_F, pos1 = -CUDART_INF_F;

    for (int ct = 0; ct < CNJT; ct++) {
        int cur = ct & 1;
        cp_wait<0>();
        __syncthreads();
        if (ct + 1 < CNJT) {
            #pragma unroll
            for (int j = 0; j < 4; j++) {
                int i = tid + j * 256;
                int r = i >> 4, c8 = i & 15;
                cp16(bsh[cur ^ 1] + (r * CPAD + c8 * 8) * 2,
                     g_h + (jsBase + (ct + 1) * 64 + r) * DDIM + c8 * 8);
            }
            cp_commit();
        }

        float acc[8][4];
        #pragma unroll
        for (int nt = 0; nt < 8; nt++)
            acc[nt][0] = acc[nt][1] = acc[nt][2] = acc[nt][3] = 0.f;

        #pragma unroll
        for (int ks = 0; ks < 8; ks++) {
            unsigned b0[8], b1[8];
            ldsm4(b0[0], b0[1], b0[2], b0[3], bsh[cur] + rowoffA + ks * 32);
            ldsm4(b0[4], b0[5], b0[6], b0[7], bsh[cur] + rowoffB + ks * 32);
            ldsm4(b1[0], b1[1], b1[2], b1[3], bsh[cur] + rowoffA + ks * 32 + 16);
            ldsm4(b1[4], b1[5], b1[6], b1[7], bsh[cur] + rowoffB + ks * 32 + 16);
            #pragma unroll
            for (int nt = 0; nt < 8; nt++)
                mma_bf16(acc[nt], a_frag[ks], b0[nt], b1[nt]);
        }

        if (ct == diagTile || ct == posTile) {
            // slow path: positive capture + diagonal mask (<=2 tiles per warp)
            int jbase = jsBase + ct * 64 + tig * 2;
            float tm0 = -CUDART_INF_F, tm1 = -CUDART_INF_F;
            #pragma unroll
            for (int nt = 0; nt < 8; nt++) {
                #pragma unroll
                for (int q = 0; q < 2; q++) {
                    int jc = jbase + nt * 8 + q;
                    float x0 = acc[nt][q];
                    float x1 = acc[nt][2 + q];
                    if (jc == p0) pos0 = x0;
                    if (jc == p1) pos1 = x1;
                    if (jc != rowG0)     tm0 = fmaxf(tm0, x0);
                    if (jc != rowG0 + 8) tm1 = fmaxf(tm1, x1);
                }
            }
            float nm0 = fmaxf(m0r, tm0), nm1 = fmaxf(m1r, tm1);
            float a0 = s0r * exp2f(m0r - nm0);
            float a1 = s1r * exp2f(m1r - nm1);
            #pragma unroll
            for (int nt = 0; nt < 8; nt++) {
                #pragma unroll
                for (int q = 0; q < 2; q++) {
                    int jc = jbase + nt * 8 + q;
                    float x0 = (jc == rowG0)     ? -CUDART_INF_F : acc[nt][q];
                    float x1 = (jc == rowG0 + 8) ? -CUDART_INF_F : acc[nt][2 + q];
                    a0 += exp2f(x0 - nm0);
                    a1 += exp2f(x1 - nm1);
                }
            }
            m0r = nm0; s0r = a0; m1r = nm1; s1r = a1;
        } else {
            // fast path: no index math, no compares
            float tm0 = -CUDART_INF_F, tm1 = -CUDART_INF_F;
            #pragma unroll
            for (int nt = 0; nt < 8; nt++) {
                tm0 = fmaxf(tm0, fmaxf(acc[nt][0], acc[nt][1]));
                tm1 = fmaxf(tm1, fmaxf(acc[nt][2], acc[nt][3]));
            }
            float nm0 = fmaxf(m0r, tm0), nm1 = fmaxf(m1r, tm1);
            float a0 = s0r * exp2f(m0r - nm0);
            float a1 = s1r * exp2f(m1r - nm1);
            #pragma unroll
            for (int nt = 0; nt < 8; nt++) {
                a0 += exp2f(acc[nt][0] - nm0) + exp2f(acc[nt][1] - nm0);
                a1 += exp2f(acc[nt][2] - nm1) + exp2f(acc[nt][3] - nm1);
            }
            m0r = nm0; s0r = a0; m1r = nm1; s1r = a1;
        }
    }

    // merge across tig (offsets 1,2)
    #pragma unroll
    for (int o = 1; o <= 2; o <<= 1) {
        float mo = __shfl_xor_sync(0xffffffffu, m0r, o);
        float so = __shfl_xor_sync(0xffffffffu, s0r, o);
        float nm = fmaxf(m0r, mo);
        s0r = s0r * exp2f(m0r - nm) + so * exp2f(mo - nm); m0r = nm;
        mo = __shfl_xor_sync(0xffffffffu, m1r, o);
        so = __shfl_xor_sync(0xffffffffu, s1r, o);
        nm = fmaxf(m1r, mo);
        s1r = s1r * exp2f(m1r - nm) + so * exp2f(mo - nm); m1r = nm;
        pos0 = fmaxf(pos0, __shfl_xor_sync(0xffffffffu, pos0, o));
        pos1 = fmaxf(pos1, __shfl_xor_sync(0xffffffffu, pos1, o));
    }
    if (tig == 0) {
        int row = js * NTOT + rowBlock + r0 + g;
        g_lm[row] = m0r; g_ls[row] = s0r; g_lp[row] = pos0;
        g_lm[row + 8] = m1r; g_ls[row + 8] = s1r; g_lp[row + 8] = pos1;
    }
}

// ---------------- graph: R13-proven body ----------------
#define KPX 40
#define GKSPLIT 8
#define GKS (KDIM / GKSPLIT)   // 1024

__global__ void __launch_bounds__(256, 2) graph_kernel(const float* __restrict__ G,
                                                       const float* __restrict__ sub_x) {
    __shared__ __nv_bfloat16 Xs[2][128 * KPX];

    int tid = threadIdx.x;
    int warp = tid >> 5, lane = tid & 31;
    int g = lane >> 2, tig = lane & 3;
    int rb  = blockIdx.x & 31;
    int ksp = blockIdx.x >> 5;
    int rowBase = rb * 128;
    int kBase   = ksp * GKS;

    float acc[16][4];
    #pragma unroll
    for (int nt = 0; nt < 16; nt++)
        acc[nt][0] = acc[nt][1] = acc[nt][2] = acc[nt][3] = 0.f;
    float rsum0 = 0.f, rsum1 = 0.f, t2p = 0.f;

    int r0 = warp * 16;
    int rowA = rowBase + r0 + g;
    int rowB = rowA + 8;
    const float* gRowA = G + (size_t)rowA * KDIM + kBase + tig * 2;
    const float* gRowB = G + (size_t)rowB * KDIM + kBase + tig * 2;
    const float* axp   = g_ax2 + kBase + tig * 2;

    unsigned xsh[2];
    xsh[0] = (unsigned)__cvta_generic_to_shared(&Xs[0][0]);
    xsh[1] = (unsigned)__cvta_generic_to_shared(&Xs[1][0]);

    #pragma unroll
    for (int j = 0; j < 2; j++) {
        int i = tid + j * 256;
        int d = i >> 2, q = i & 3;
        cp16(xsh[0] + (d * KPX + q * 8) * 2, g_axT + d * KDIM + kBase + q * 8);
    }
    cp_commit();

    float2 bA0 = *reinterpret_cast<const float2*>(gRowA);
    float2 bB0 = *reinterpret_cast<const float2*>(gRowB);
    float2 bA1 = *reinterpret_cast<const float2*>(gRowA + 8);
    float2 bB1 = *reinterpret_cast<const float2*>(gRowB + 8);

    for (int kt = 0; kt < GKS / 32; kt++) {
        int cur = kt & 1;
        cp_wait<0>();
        __syncthreads();
        if (kt + 1 < GKS / 32) {
            #pragma unroll
            for (int j = 0; j < 2; j++) {
                int i = tid + j * 256;
                int d = i >> 2, q = i & 3;
                cp16(xsh[cur ^ 1] + (d * KPX + q * 8) * 2,
                     g_axT + d * KDIM + kBase + (kt + 1) * 32 + q * 8);
            }
            cp_commit();
        }

        #pragma unroll
        for (int ks = 0; ks < 2; ks++) {
            int kk = kt * 2 + ks;
            float2 vA0 = bA0, vB0 = bB0, vA1 = bA1, vB1 = bB1;
            int ncol = (kk + 1 < GKS / 16) ? (kk + 1) * 16 : 0;
            bA0 = *reinterpret_cast<const float2*>(gRowA + ncol);
            bB0 = *reinterpret_cast<const float2*>(gRowB + ncol);
            bA1 = *reinterpret_cast<const float2*>(gRowA + ncol + 8);
            bB1 = *reinterpret_cast<const float2*>(gRowB + ncol + 8);

            rsum0 += vA0.x + vA0.y + vA1.x + vA1.y;
            rsum1 += vB0.x + vB0.y + vB1.x + vB1.y;

            float2 w0 = *reinterpret_cast<const float2*>(axp + kk * 16);
            float2 w1 = *reinterpret_cast<const float2*>(axp + kk * 16 + 8);
            t2p += (vA0.x + vB0.x) * w0.x + (vA0.y + vB0.y) * w0.y
                 + (vA1.x + vB1.x) * w1.x + (vA1.y + vB1.y) * w1.y;

            unsigned af[4];
            af[0] = pack_bf2(vA0.x, vA0.y);
            af[1] = pack_bf2(vB0.x, vB0.y);
            af[2] = pack_bf2(vA1.x, vA1.y);
            af[3] = pack_bf2(vB1.x, vB1.y);
            #pragma unroll
            for (int nt = 0; nt < 16; nt++) {
                const __nv_bfloat16* bp = &Xs[cur][(nt * 8 + g) * KPX + ks * 16 + tig * 2];
                unsigned b0 = *reinterpret_cast<const unsigned*>(bp);
                unsigned b1 = *reinterpret_cast<const unsigned*>(bp + 8);
                mma_bf16(acc[nt], af, b0, b1);
            }
        }
    }

    float t3p = 0.f;
    #pragma unroll
    for (int nt = 0; nt < 16; nt++) {
        int d = nt * 8 + tig * 2;
        float2 s0 = *reinterpret_cast<const float2*>(sub_x + rowA * DDIM + d);
        float2 s1 = *reinterpret_cast<const float2*>(sub_x + rowB * DDIM + d);
        t3p += acc[nt][0] * s0.x + acc[nt][1] * s0.y + acc[nt][2] * s1.x + acc[nt][3] * s1.y;
    }
    #pragma unroll
    for (int o = 16; o; o >>= 1) t3p += __shfl_xor_sync(0xffffffffu, t3p, o);
    if (lane == 0) atomicAdd(&g_acc[2], t3p);

    #pragma unroll
    for (int o = 16; o; o >>= 1) t2p += __shfl_xor_sync(0xffffffffu, t2p, o);
    if (lane == 0) atomicAdd(&g_acc[3], t2p);

    rsum0 += __shfl_xor_sync(0xffffffffu, rsum0, 1);
    rsum0 += __shfl_xor_sync(0xffffffffu, rsum0, 2);
    rsum1 += __shfl_xor_sync(0xffffffffu, rsum1, 1);
    rsum1 += __shfl_xor_sync(0xffffffffu, rsum1, 2);
    float t1p = 0.f;
    if (tig == 0) t1p = rsum0 * g_xs2[rowA] + rsum1 * g_xs2[rowB];
    #pragma unroll
    for (int o = 4; o <= 16; o <<= 1) t1p += __shfl_xor_sync(0xffffffffu, t1p, o);
    if (lane == 0) atomicAdd(&g_acc[1], t1p);
}

// ---------------- finalize ----------------
__global__ void __launch_bounds__(256) finalize_kernel(float* __restrict__ out) {
    __shared__ float red[8];
    int tid = threadIdx.x;
    float csum = 0.f;
    for (int r = tid; r < NTOT; r += 256) {
        float m = g_lm[r], s = g_ls[r], p = g_lp[r];
        #pragma unroll
        for (int js = 1; js < NJS; js++) {
            float mo = g_lm[js * NTOT + r], so = g_ls[js * NTOT + r];
            float nm = fmaxf(m, mo);
            s = s * exp2f(m - nm) + so * exp2f(mo - nm);
            m = nm;
            p = fmaxf(p, g_lp[js * NTOT + r]);
        }
        csum += LN2F * (m + log2f(s) - p);
    }
    #pragma unroll
    for (int o = 16; o; o >>= 1) csum += __shfl_xor_sync(0xffffffffu, csum, o);
    if ((tid & 31) == 0) red[tid >> 5] = csum;
    __syncthreads();
    if (tid == 0) {
        float cs = 0.f;
        #pragma unroll
        for (int i = 0; i < 8; i++) cs += red[i];
        float contr = cs / (float)NTOT;
        float graph = (g_acc[1] + g_acc[3] - 2.0f * g_acc[2]) / ((float)BHALF * (float)KDIM);
        out[0] = contr + graph;
    }
}

// ---------------- launch: fork-join overlap of the two big kernels ----------------
extern "C" void kernel_launch(void* const* d_in, const int* in_sizes, int n_in,
                              void* d_out, int out_size) {
    (void)in_sizes; (void)n_in; (void)out_size;
    const float* h_i   = (const float*)d_in[0];
    const float* h_j   = (const float*)d_in[1];
    const float* G     = (const float*)d_in[2];
    const float* sub_x = (const float*)d_in[3];
    const float* all_x = (const float*)d_in[4];
    float* out = (float*)d_out;

    // created once, outside any capture (first call is the uncaptured correctness run)
    static cudaStream_t s2 = nullptr;
    static cudaEvent_t evFork = nullptr, evJoin = nullptr;
    if (s2 == nullptr) {
        cudaStreamCreateWithFlags(&s2, cudaStreamNonBlocking);
        cudaEventCreateWithFlags(&evFork, cudaEventDisableTiming);
        cudaEventCreateWithFlags(&evJoin, cudaEventDisableTiming);
    }

    prep_kernel<<<512, 256>>>(h_i, h_j, sub_x, all_x);
    transpose_ax<<<dim3(256, 4), 256>>>(all_x);

    cudaEventRecord(evFork, 0);
    cudaStreamWaitEvent(s2, evFork, 0);
    graph_kernel<<<256, 256, 0, s2>>>(G, sub_x);       // DRAM-bound branch
    cudaEventRecord(evJoin, s2);

    contrastive_kernel<<<256, 256>>>();                 // tensor/MUFU-bound branch

    cudaStreamWaitEvent(0, evJoin, 0);
    finalize_kernel<<<1, 256>>>(out);
}

// round 15
// speedup vs baseline: 1.1861x; 1.0864x over previous
#include <cuda_runtime.h>
#include <cuda_bf16.h>
#include <math_constants.h>
#include <math.h>

#define NTOT  8192
#define BHALF 4096
#define DDIM  128
#define KDIM  8192
#define NJS   4
#define LN2F  0.69314718055994531f
#define COFF  160.0f            // fixed LSE offset (log2 domain)

// ---------------- device scratch ----------------
__device__ __nv_bfloat16 g_h[NTOT * DDIM];        // concat(h_i,h_j) * sqrt(2*log2e)
__device__ __nv_bfloat16 g_axT[DDIM * KDIM];
__device__ float g_xs2[BHALF];
__device__ float g_ax2[KDIM];
__device__ float g_acc[4];                        // 1: t1, 2: t3, 3: t2
__device__ float g_ls[NJS * NTOT];                // per-jsplit row sum of exp2(x-COFF)
__device__ float g_lp[NJS * NTOT];                // per-jsplit row positive (log2 dom)

// ---------------- helpers ----------------
__device__ __forceinline__ void mma_bf16(float* c, const unsigned* a, unsigned b0, unsigned b1) {
    asm volatile(
        "mma.sync.aligned.m16n8k16.row.col.f32.bf16.bf16.f32 "
        "{%0,%1,%2,%3}, {%4,%5,%6,%7}, {%8,%9}, {%0,%1,%2,%3};\n"
        : "+f"(c[0]), "+f"(c[1]), "+f"(c[2]), "+f"(c[3])
        : "r"(a[0]), "r"(a[1]), "r"(a[2]), "r"(a[3]), "r"(b0), "r"(b1));
}
__device__ __forceinline__ unsigned pack_bf2(float x, float y) {
    __nv_bfloat162 b = __floats2bfloat162_rn(x, y);
    return *reinterpret_cast<unsigned*>(&b);
}
__device__ __forceinline__ void cp16(unsigned dst, const void* src) {
    asm volatile("cp.async.cg.shared.global [%0], [%1], 16;\n" :: "r"(dst), "l"(src));
}
__device__ __forceinline__ void cp_commit() { asm volatile("cp.async.commit_group;\n"); }
template<int N> __device__ __forceinline__ void cp_wait() {
    asm volatile("cp.async.wait_group %0;\n" :: "n"(N));
}
__device__ __forceinline__ void ldsm4(unsigned& r0, unsigned& r1, unsigned& r2, unsigned& r3,
                                      unsigned addr) {
    asm volatile("ldmatrix.sync.aligned.m8n8.x4.shared.b16 {%0,%1,%2,%3}, [%4];\n"
        : "=r"(r0), "=r"(r1), "=r"(r2), "=r"(r3) : "r"(addr));
}

// ---------------- prep ----------------
__global__ void __launch_bounds__(256) prep_kernel(const float* __restrict__ h_i,
                                                   const float* __restrict__ h_j,
                                                   const float* __restrict__ sub_x,
                                                   const float* __restrict__ all_x) {
    const float S = 1.69864360f;   // sqrt(2 * log2(e))
    int tid = blockIdx.x * blockDim.x + threadIdx.x;
    int nth = gridDim.x * blockDim.x;

    int nh2 = NTOT * DDIM / 2;
    for (int idx = tid; idx < nh2; idx += nth) {
        int el  = idx << 1;
        int row = el >> 7;
        int col = el & 127;
        const float* src = (row < BHALF) ? (h_i + row * DDIM + col)
                                         : (h_j + (row - BHALF) * DDIM + col);
        float2 v = *reinterpret_cast<const float2*>(src);
        reinterpret_cast<__nv_bfloat162*>(g_h)[idx] = __floats2bfloat162_rn(v.x * S, v.y * S);
    }

    int wid = tid >> 5, lane = tid & 31, nw = nth >> 5;
    for (int r = wid; r < BHALF; r += nw) {
        float4 a = reinterpret_cast<const float4*>(sub_x + r * DDIM)[lane];
        float s = a.x*a.x + a.y*a.y + a.z*a.z + a.w*a.w;
        #pragma unroll
        for (int o = 16; o; o >>= 1) s += __shfl_xor_sync(0xffffffffu, s, o);
        if (lane == 0) g_xs2[r] = s;
    }
    for (int r = wid; r < KDIM; r += nw) {
        float4 a = reinterpret_cast<const float4*>(all_x + r * DDIM)[lane];
        float s = a.x*a.x + a.y*a.y + a.z*a.z + a.w*a.w;
        #pragma unroll
        for (int o = 16; o; o >>= 1) s += __shfl_xor_sync(0xffffffffu, s, o);
        if (lane == 0) g_ax2[r] = s;
    }

    if (blockIdx.x == 0 && tid < 4) g_acc[tid] = 0.f;
}

// ---------------- transpose all_x -> g_axT[d][k] ----------------
__global__ void __launch_bounds__(256) transpose_ax(const float* __restrict__ all_x) {
    __shared__ float t[32][33];
    int k0 = blockIdx.x * 32;
    int d0 = blockIdx.y * 32;
    int tx = threadIdx.x & 31, ty = threadIdx.x >> 5;
    #pragma unroll
    for (int j = 0; j < 4; j++) {
        int k = k0 + ty + j * 8;
        t[ty + j * 8][tx] = all_x[k * DDIM + d0 + tx];
    }
    __syncthreads();
    #pragma unroll
    for (int j = 0; j < 4; j++) {
        int d = d0 + ty + j * 8;
        g_axT[d * KDIM + k0 + tx] = __float2bfloat16(t[tx][ty + j * 8]);
    }
}

// ---------------- fused big kernel: even bid = contrastive, odd bid = graph ----------------
#define CPAD 136
#define CNJT (NTOT / NJS / 64)   // 32 tiles per split
#define KPX 40
#define GKSPLIT 8
#define GKS (KDIM / GKSPLIT)     // 1024

struct SmemC { __nv_bfloat16 bs[2][64 * CPAD]; };   // 34816 B
struct SmemG { __nv_bfloat16 xs[2][128 * KPX]; };   // 20480 B
union SmemU { SmemC c; SmemG g; };

__device__ __forceinline__ void contrastive_body(SmemU* sm, int cb) {
    int tid = threadIdx.x;
    int warp = tid >> 5, lane = tid & 31;
    int g = lane >> 2, tig = lane & 3;
    int rb = cb & 63;
    int js = cb >> 6;                   // 0..3
    int jsBase = js * (NTOT / NJS);
    int rowBlock = rb * 128;
    int r0 = warp * 16;
    int rowG0 = rowBlock + r0 + g;
    int p0 = (rowG0 + BHALF) & (NTOT - 1);
    int p1 = (rowG0 + 8 + BHALF) & (NTOT - 1);

    int bandBase = rowBlock + r0;
    int pBand = (bandBase + BHALF) & (NTOT - 1);
    bool dIn = ((unsigned)(bandBase - jsBase)) < (unsigned)(NTOT / NJS);
    bool pIn = ((unsigned)(pBand - jsBase))    < (unsigned)(NTOT / NJS);
    int diagTile = dIn ? ((bandBase - jsBase) >> 6) : -1;
    int posTile  = pIn ? ((pBand - jsBase) >> 6)    : -2;

    unsigned a_frag[8][4];
    #pragma unroll
    for (int ks = 0; ks < 8; ks++) {
        int kc = ks * 16 + tig * 2;
        a_frag[ks][0] = *reinterpret_cast<const unsigned*>(g_h + rowG0 * DDIM + kc);
        a_frag[ks][1] = *reinterpret_cast<const unsigned*>(g_h + (rowG0 + 8) * DDIM + kc);
        a_frag[ks][2] = *reinterpret_cast<const unsigned*>(g_h + rowG0 * DDIM + kc + 8);
        a_frag[ks][3] = *reinterpret_cast<const unsigned*>(g_h + (rowG0 + 8) * DDIM + kc + 8);
    }

    unsigned bsh[2];
    bsh[0] = (unsigned)__cvta_generic_to_shared(&sm->c.bs[0][0]);
    bsh[1] = (unsigned)__cvta_generic_to_shared(&sm->c.bs[1][0]);

    unsigned rowoffA = (unsigned)((((lane >> 3) * 8) + (lane & 7)) * CPAD * 2);
    unsigned rowoffB = rowoffA + 32u * CPAD * 2;

    #pragma unroll
    for (int j = 0; j < 4; j++) {
        int i = tid + j * 256;
        int r = i >> 4, c8 = i & 15;
        cp16(bsh[0] + (r * CPAD + c8 * 8) * 2, g_h + (jsBase + r) * DDIM + c8 * 8);
    }
    cp_commit();

    float s0r = 0.f, s1r = 0.f;
    float pos0 = -CUDART_INF_F, pos1 = -CUDART_INF_F;

    for (int ct = 0; ct < CNJT; ct++) {
        int cur = ct & 1;
        cp_wait<0>();
        __syncthreads();
        if (ct + 1 < CNJT) {
            #pragma unroll
            for (int j = 0; j < 4; j++) {
                int i = tid + j * 256;
                int r = i >> 4, c8 = i & 15;
                cp16(bsh[cur ^ 1] + (r * CPAD + c8 * 8) * 2,
                     g_h + (jsBase + (ct + 1) * 64 + r) * DDIM + c8 * 8);
            }
            cp_commit();
        }

        float acc[8][4];
        #pragma unroll
        for (int nt = 0; nt < 8; nt++)
            acc[nt][0] = acc[nt][1] = acc[nt][2] = acc[nt][3] = 0.f;

        #pragma unroll
        for (int ks = 0; ks < 8; ks++) {
            unsigned b0[8], b1[8];
            ldsm4(b0[0], b0[1], b0[2], b0[3], bsh[cur] + rowoffA + ks * 32);
            ldsm4(b0[4], b0[5], b0[6], b0[7], bsh[cur] + rowoffB + ks * 32);
            ldsm4(b1[0], b1[1], b1[2], b1[3], bsh[cur] + rowoffA + ks * 32 + 16);
            ldsm4(b1[4], b1[5], b1[6], b1[7], bsh[cur] + rowoffB + ks * 32 + 16);
            #pragma unroll
            for (int nt = 0; nt < 8; nt++)
                mma_bf16(acc[nt], a_frag[ks], b0[nt], b1[nt]);
        }

        if (ct == diagTile || ct == posTile) {
            // slow path: capture positives, mask diagonal, fixed-offset accumulate
            int jbase = jsBase + ct * 64 + tig * 2;
            float a0 = 0.f, a1 = 0.f;
            #pragma unroll
            for (int nt = 0; nt < 8; nt++) {
                #pragma unroll
                for (int q = 0; q < 2; q++) {
                    int jc = jbase + nt * 8 + q;
                    float x0 = acc[nt][q];
                    float x1 = acc[nt][2 + q];
                    if (jc == p0) pos0 = x0;
                    if (jc == p1) pos1 = x1;
                    if (jc == rowG0)     x0 = -CUDART_INF_F;
                    if (jc == rowG0 + 8) x1 = -CUDART_INF_F;
                    a0 += exp2f(x0 - COFF);
                    a1 += exp2f(x1 - COFF);
                }
            }
            s0r += a0; s1r += a1;
        } else {
            // fast path: pure exp2-accumulate, no compares, no max
            float a0 = 0.f, a1 = 0.f;
            #pragma unroll
            for (int nt = 0; nt < 8; nt++) {
                a0 += exp2f(acc[nt][0] - COFF) + exp2f(acc[nt][1] - COFF);
                a1 += exp2f(acc[nt][2] - COFF) + exp2f(acc[nt][3] - COFF);
            }
            s0r += a0; s1r += a1;
        }
    }

    // merge across tig: plain sum (fixed offset), max for positives
    #pragma unroll
    for (int o = 1; o <= 2; o <<= 1) {
        s0r += __shfl_xor_sync(0xffffffffu, s0r, o);
        s1r += __shfl_xor_sync(0xffffffffu, s1r, o);
        pos0 = fmaxf(pos0, __shfl_xor_sync(0xffffffffu, pos0, o));
        pos1 = fmaxf(pos1, __shfl_xor_sync(0xffffffffu, pos1, o));
    }
    if (tig == 0) {
        int row = js * NTOT + rowBlock + r0 + g;
        g_ls[row] = s0r; g_lp[row] = pos0;
        g_ls[row + 8] = s1r; g_lp[row + 8] = pos1;
    }
}

__device__ __forceinline__ void graph_body(SmemU* sm, int gb,
                                           const float* __restrict__ G,
                                           const float* __restrict__ sub_x) {
    int tid = threadIdx.x;
    int warp = tid >> 5, lane = tid & 31;
    int g = lane >> 2, tig = lane & 3;
    int rb  = gb & 31;
    int ksp = gb >> 5;
    int rowBase = rb * 128;
    int kBase   = ksp * GKS;

    float acc[16][4];
    #pragma unroll
    for (int nt = 0; nt < 16; nt++)
        acc[nt][0] = acc[nt][1] = acc[nt][2] = acc[nt][3] = 0.f;
    float rsum0 = 0.f, rsum1 = 0.f, t2p = 0.f;

    int r0 = warp * 16;
    int rowA = rowBase + r0 + g;
    int rowB = rowA + 8;
    const float* gRowA = G + (size_t)rowA * KDIM + kBase + tig * 2;
    const float* gRowB = G + (size_t)rowB * KDIM + kBase + tig * 2;
    const float* axp   = g_ax2 + kBase + tig * 2;

    unsigned xsh[2];
    xsh[0] = (unsigned)__cvta_generic_to_shared(&sm->g.xs[0][0]);
    xsh[1] = (unsigned)__cvta_generic_to_shared(&sm->g.xs[1][0]);

    #pragma unroll
    for (int j = 0; j < 2; j++) {
        int i = tid + j * 256;
        int d = i >> 2, q = i & 3;
        cp16(xsh[0] + (d * KPX + q * 8) * 2, g_axT + d * KDIM + kBase + q * 8);
    }
    cp_commit();

    float2 bA0 = *reinterpret_cast<const float2*>(gRowA);
    float2 bB0 = *reinterpret_cast<const float2*>(gRowB);
    float2 bA1 = *reinterpret_cast<const float2*>(gRowA + 8);
    float2 bB1 = *reinterpret_cast<const float2*>(gRowB + 8);

    for (int kt = 0; kt < GKS / 32; kt++) {
        int cur = kt & 1;
        cp_wait<0>();
        __syncthreads();
        if (kt + 1 < GKS / 32) {
            #pragma unroll
            for (int j = 0; j < 2; j++) {
                int i = tid + j * 256;
                int d = i >> 2, q = i & 3;
                cp16(xsh[cur ^ 1] + (d * KPX + q * 8) * 2,
                     g_axT + d * KDIM + kBase + (kt + 1) * 32 + q * 8);
            }
            cp_commit();
        }

        #pragma unroll
        for (int ks = 0; ks < 2; ks++) {
            int kk = kt * 2 + ks;
            float2 vA0 = bA0, vB0 = bB0, vA1 = bA1, vB1 = bB1;
            int ncol = (kk + 1 < GKS / 16) ? (kk + 1) * 16 : 0;
            bA0 = *reinterpret_cast<const float2*>(gRowA + ncol);
            bB0 = *reinterpret_cast<const float2*>(gRowB + ncol);
            bA1 = *reinterpret_cast<const float2*>(gRowA + ncol + 8);
            bB1 = *reinterpret_cast<const float2*>(gRowB + ncol + 8);

            rsum0 += vA0.x + vA0.y + vA1.x + vA1.y;
            rsum1 += vB0.x + vB0.y + vB1.x + vB1.y;

            float2 w0 = *reinterpret_cast<const float2*>(axp + kk * 16);
            float2 w1 = *reinterpret_cast<const float2*>(axp + kk * 16 + 8);
            t2p += (vA0.x + vB0.x) * w0.x + (vA0.y + vB0.y) * w0.y
                 + (vA1.x + vB1.x) * w1.x + (vA1.y + vB1.y) * w1.y;

            unsigned af[4];
            af[0] = pack_bf2(vA0.x, vA0.y);
            af[1] = pack_bf2(vB0.x, vB0.y);
            af[2] = pack_bf2(vA1.x, vA1.y);
            af[3] = pack_bf2(vB1.x, vB1.y);
            #pragma unroll
            for (int nt = 0; nt < 16; nt++) {
                const __nv_bfloat16* bp = &sm->g.xs[cur][(nt * 8 + g) * KPX + ks * 16 + tig * 2];
                unsigned b0 = *reinterpret_cast<const unsigned*>(bp);
                unsigned b1 = *reinterpret_cast<const unsigned*>(bp + 8);
                mma_bf16(acc[nt], af, b0, b1);
            }
        }
    }

    float t3p = 0.f;
    #pragma unroll
    for (int nt = 0; nt < 16; nt++) {
        int d = nt * 8 + tig * 2;
        float2 s0 = *reinterpret_cast<const float2*>(sub_x + rowA * DDIM + d);
        float2 s1 = *reinterpret_cast<const float2*>(sub_x + rowB * DDIM + d);
        t3p += acc[nt][0] * s0.x + acc[nt][1] * s0.y + acc[nt][2] * s1.x + acc[nt][3] * s1.y;
    }
    #pragma unroll
    for (int o = 16; o; o >>= 1) t3p += __shfl_xor_sync(0xffffffffu, t3p, o);
    if (lane == 0) atomicAdd(&g_acc[2], t3p);

    #pragma unroll
    for (int o = 16; o; o >>= 1) t2p += __shfl_xor_sync(0xffffffffu, t2p, o);
    if (lane == 0) atomicAdd(&g_acc[3], t2p);

    rsum0 += __shfl_xor_sync(0xffffffffu, rsum0, 1);
    rsum0 += __shfl_xor_sync(0xffffffffu, rsum0, 2);
    rsum1 += __shfl_xor_sync(0xffffffffu, rsum1, 1);
    rsum1 += __shfl_xor_sync(0xffffffffu, rsum1, 2);
    float t1p = 0.f;
    if (tig == 0) t1p = rsum0 * g_xs2[rowA] + rsum1 * g_xs2[rowB];
    #pragma unroll
    for (int o = 4; o <= 16; o <<= 1) t1p += __shfl_xor_sync(0xffffffffu, t1p, o);
    if (lane == 0) atomicAdd(&g_acc[1], t1p);
}

__global__ void __launch_bounds__(256, 2) fused_kernel(const float* __restrict__ G,
                                                       const float* __restrict__ sub_x) {
    __shared__ SmemU sm;
    if (blockIdx.x & 1) graph_body(&sm, blockIdx.x >> 1, G, sub_x);
    else                contrastive_body(&sm, blockIdx.x >> 1);
}

// ---------------- finalize: fixed-offset LSE + combine ----------------
__global__ void __launch_bounds__(256) finalize_kernel(float* __restrict__ out) {
    __shared__ float red[8];
    int tid = threadIdx.x;
    float csum = 0.f;
    for (int r = tid; r < NTOT; r += 256) {
        float s = g_ls[r], p = g_lp[r];
        #pragma unroll
        for (int js = 1; js < NJS; js++) {
            s += g_ls[js * NTOT + r];
            p = fmaxf(p, g_lp[js * NTOT + r]);
        }
        csum += LN2F * (COFF + log2f(s) - p);
    }
    #pragma unroll
    for (int o = 16; o; o >>= 1) csum += __shfl_xor_sync(0xffffffffu, csum, o);
    if ((tid & 31) == 0) red[tid >> 5] = csum;
    __syncthreads();
    if (tid == 0) {
        float cs = 0.f;
        #pragma unroll
        for (int i = 0; i < 8; i++) cs += red[i];
        float contr = cs / (float)NTOT;
        float graph = (g_acc[1] + g_acc[3] - 2.0f * g_acc[2]) / ((float)BHALF * (float)KDIM);
        out[0] = contr + graph;
    }
}

// ---------------- launch ----------------
extern "C" void kernel_launch(void* const* d_in, const int* in_sizes, int n_in,
                              void* d_out, int out_size) {
    (void)in_sizes; (void)n_in; (void)out_size;
    const float* h_i   = (const float*)d_in[0];
    const float* h_j   = (const float*)d_in[1];
    const float* G     = (const float*)d_in[2];
    const float* sub_x = (const float*)d_in[3];
    const float* all_x = (const float*)d_in[4];
    float* out = (float*)d_out;

    prep_kernel<<<512, 256>>>(h_i, h_j, sub_x, all_x);
    transpose_ax<<<dim3(256, 4), 256>>>(all_x);
    fused_kernel<<<512, 256>>>(G, sub_x);
    finalize_kernel<<<1, 256>>>(out);
}

// round 16
// speedup vs baseline: 1.2591x; 1.0616x over previous
#include <cuda_runtime.h>
#include <cuda_bf16.h>
#include <math_constants.h>
#include <math.h>

#define NTOT  8192
#define BHALF 4096
#define DDIM  128
#define KDIM  8192
#define NJS   4
#define LN2F  0.69314718055994531f
#define COFF  160.0f            // fixed LSE offset (log2 domain)

// ---------------- device scratch ----------------
__device__ __nv_bfloat16 g_h[NTOT * DDIM];        // concat(h_i,h_j) * sqrt(2*log2e)
__device__ __nv_bfloat16 g_axT[DDIM * KDIM];
__device__ float g_xs2[BHALF];
__device__ float g_ax2[KDIM];
__device__ float g_acc[4];                        // 1: t1, 2: t3, 3: t2
__device__ float g_ls[NJS * NTOT];                // per-jsplit row sum of exp2(x-COFF)
__device__ float g_lp[NJS * NTOT];                // per-jsplit row positive (log2 dom)
__device__ float g_csum;                          // contrastive partial sum
__device__ unsigned g_ctr;                        // finalize last-block counter

// ---------------- helpers ----------------
__device__ __forceinline__ void mma_bf16(float* c, const unsigned* a, unsigned b0, unsigned b1) {
    asm volatile(
        "mma.sync.aligned.m16n8k16.row.col.f32.bf16.bf16.f32 "
        "{%0,%1,%2,%3}, {%4,%5,%6,%7}, {%8,%9}, {%0,%1,%2,%3};\n"
        : "+f"(c[0]), "+f"(c[1]), "+f"(c[2]), "+f"(c[3])
        : "r"(a[0]), "r"(a[1]), "r"(a[2]), "r"(a[3]), "r"(b0), "r"(b1));
}
__device__ __forceinline__ unsigned pack_bf2(float x, float y) {
    __nv_bfloat162 b = __floats2bfloat162_rn(x, y);
    return *reinterpret_cast<unsigned*>(&b);
}
__device__ __forceinline__ void cp16(unsigned dst, const void* src) {
    asm volatile("cp.async.cg.shared.global [%0], [%1], 16;\n" :: "r"(dst), "l"(src));
}
__device__ __forceinline__ void cp_commit() { asm volatile("cp.async.commit_group;\n"); }
template<int N> __device__ __forceinline__ void cp_wait() {
    asm volatile("cp.async.wait_group %0;\n" :: "n"(N));
}
__device__ __forceinline__ void ldsm4(unsigned& r0, unsigned& r1, unsigned& r2, unsigned& r3,
                                      unsigned addr) {
    asm volatile("ldmatrix.sync.aligned.m8n8.x4.shared.b16 {%0,%1,%2,%3}, [%4];\n"
        : "=r"(r0), "=r"(r1), "=r"(r2), "=r"(r3) : "r"(addr));
}

// ---------------- prep + transpose fused ----------------
// bids [0,512): h concat/scale->bf16, norms, zero accumulators
// bids [512,1536): transpose all_x -> g_axT[d][k]
__global__ void __launch_bounds__(256) prep_kernel(const float* __restrict__ h_i,
                                                   const float* __restrict__ h_j,
                                                   const float* __restrict__ sub_x,
                                                   const float* __restrict__ all_x) {
    int bid = blockIdx.x;
    int tidl = threadIdx.x;

    if (bid >= 512) {
        __shared__ float t[32][33];
        int b = bid - 512;                       // 1024 blocks: (256 k-tiles, 4 d-tiles)
        int k0 = (b & 255) * 32;
        int d0 = (b >> 8) * 32;
        int tx = tidl & 31, ty = tidl >> 5;
        #pragma unroll
        for (int j = 0; j < 4; j++) {
            int k = k0 + ty + j * 8;
            t[ty + j * 8][tx] = all_x[k * DDIM + d0 + tx];
        }
        __syncthreads();
        #pragma unroll
        for (int j = 0; j < 4; j++) {
            int d = d0 + ty + j * 8;
            g_axT[d * KDIM + k0 + tx] = __float2bfloat16(t[tx][ty + j * 8]);
        }
        return;
    }

    const float S = 1.69864360f;   // sqrt(2 * log2(e))
    int tid = bid * 256 + tidl;
    const int nth = 512 * 256;

    int nh2 = NTOT * DDIM / 2;
    for (int idx = tid; idx < nh2; idx += nth) {
        int el  = idx << 1;
        int row = el >> 7;
        int col = el & 127;
        const float* src = (row < BHALF) ? (h_i + row * DDIM + col)
                                         : (h_j + (row - BHALF) * DDIM + col);
        float2 v = *reinterpret_cast<const float2*>(src);
        reinterpret_cast<__nv_bfloat162*>(g_h)[idx] = __floats2bfloat162_rn(v.x * S, v.y * S);
    }

    int wid = tid >> 5, lane = tid & 31, nw = nth >> 5;
    for (int r = wid; r < BHALF; r += nw) {
        float4 a = reinterpret_cast<const float4*>(sub_x + r * DDIM)[lane];
        float s = a.x*a.x + a.y*a.y + a.z*a.z + a.w*a.w;
        #pragma unroll
        for (int o = 16; o; o >>= 1) s += __shfl_xor_sync(0xffffffffu, s, o);
        if (lane == 0) g_xs2[r] = s;
    }
    for (int r = wid; r < KDIM; r += nw) {
        float4 a = reinterpret_cast<const float4*>(all_x + r * DDIM)[lane];
        float s = a.x*a.x + a.y*a.y + a.z*a.z + a.w*a.w;
        #pragma unroll
        for (int o = 16; o; o >>= 1) s += __shfl_xor_sync(0xffffffffu, s, o);
        if (lane == 0) g_ax2[r] = s;
    }

    if (bid == 0 && tidl < 4) g_acc[tidl] = 0.f;
    if (bid == 0 && tidl == 4) { g_csum = 0.f; g_ctr = 0u; }
}

// ---------------- fused big kernel: even bid = contrastive, odd bid = graph ----------------
#define CPAD 136
#define CNJT (NTOT / NJS / 64)   // 32 tiles per split
#define KPX 40
#define GKSPLIT 8
#define GKS (KDIM / GKSPLIT)     // 1024

struct SmemC { __nv_bfloat16 bs[2][64 * CPAD]; };   // 34816 B
struct SmemG { __nv_bfloat16 xs[2][128 * KPX]; };   // 20480 B
union SmemU { SmemC c; SmemG g; };

__device__ __forceinline__ void contrastive_body(SmemU* sm, int cb) {
    int tid = threadIdx.x;
    int warp = tid >> 5, lane = tid & 31;
    int g = lane >> 2, tig = lane & 3;
    int rb = cb & 63;
    int js = cb >> 6;                   // 0..3
    int jsBase = js * (NTOT / NJS);
    int rowBlock = rb * 128;
    int r0 = warp * 16;
    int rowG0 = rowBlock + r0 + g;
    int p0 = (rowG0 + BHALF) & (NTOT - 1);
    int p1 = (rowG0 + 8 + BHALF) & (NTOT - 1);

    int bandBase = rowBlock + r0;
    int pBand = (bandBase + BHALF) & (NTOT - 1);
    bool dIn = ((unsigned)(bandBase - jsBase)) < (unsigned)(NTOT / NJS);
    bool pIn = ((unsigned)(pBand - jsBase))    < (unsigned)(NTOT / NJS);
    int diagTile = dIn ? ((bandBase - jsBase) >> 6) : -1;
    int posTile  = pIn ? ((pBand - jsBase) >> 6)    : -2;

    unsigned a_frag[8][4];
    #pragma unroll
    for (int ks = 0; ks < 8; ks++) {
        int kc = ks * 16 + tig * 2;
        a_frag[ks][0] = *reinterpret_cast<const unsigned*>(g_h + rowG0 * DDIM + kc);
        a_frag[ks][1] = *reinterpret_cast<const unsigned*>(g_h + (rowG0 + 8) * DDIM + kc);
        a_frag[ks][2] = *reinterpret_cast<const unsigned*>(g_h + rowG0 * DDIM + kc + 8);
        a_frag[ks][3] = *reinterpret_cast<const unsigned*>(g_h + (rowG0 + 8) * DDIM + kc + 8);
    }

    unsigned bsh[2];
    bsh[0] = (unsigned)__cvta_generic_to_shared(&sm->c.bs[0][0]);
    bsh[1] = (unsigned)__cvta_generic_to_shared(&sm->c.bs[1][0]);

    unsigned rowoffA = (unsigned)((((lane >> 3) * 8) + (lane & 7)) * CPAD * 2);
    unsigned rowoffB = rowoffA + 32u * CPAD * 2;

    #pragma unroll
    for (int j = 0; j < 4; j++) {
        int i = tid + j * 256;
        int r = i >> 4, c8 = i & 15;
        cp16(bsh[0] + (r * CPAD + c8 * 8) * 2, g_h + (jsBase + r) * DDIM + c8 * 8);
    }
    cp_commit();

    float s0r = 0.f, s1r = 0.f;
    float pos0 = -CUDART_INF_F, pos1 = -CUDART_INF_F;

    for (int ct = 0; ct < CNJT; ct++) {
        int cur = ct & 1;
        cp_wait<0>();
        __syncthreads();
        if (ct + 1 < CNJT) {
            #pragma unroll
            for (int j = 0; j < 4; j++) {
                int i = tid + j * 256;
                int r = i >> 4, c8 = i & 15;
                cp16(bsh[cur ^ 1] + (r * CPAD + c8 * 8) * 2,
                     g_h + (jsBase + (ct + 1) * 64 + r) * DDIM + c8 * 8);
            }
            cp_commit();
        }

        float acc[8][4];
        #pragma unroll
        for (int nt = 0; nt < 8; nt++)
            acc[nt][0] = acc[nt][1] = acc[nt][2] = acc[nt][3] = 0.f;

        #pragma unroll
        for (int ks = 0; ks < 8; ks++) {
            unsigned b0[8], b1[8];
            ldsm4(b0[0], b0[1], b0[2], b0[3], bsh[cur] + rowoffA + ks * 32);
            ldsm4(b0[4], b0[5], b0[6], b0[7], bsh[cur] + rowoffB + ks * 32);
            ldsm4(b1[0], b1[1], b1[2], b1[3], bsh[cur] + rowoffA + ks * 32 + 16);
            ldsm4(b1[4], b1[5], b1[6], b1[7], bsh[cur] + rowoffB + ks * 32 + 16);
            #pragma unroll
            for (int nt = 0; nt < 8; nt++)
                mma_bf16(acc[nt], a_frag[ks], b0[nt], b1[nt]);
        }

        if (ct == diagTile || ct == posTile) {
            int jbase = jsBase + ct * 64 + tig * 2;
            float a0 = 0.f, a1 = 0.f;
            #pragma unroll
            for (int nt = 0; nt < 8; nt++) {
                #pragma unroll
                for (int q = 0; q < 2; q++) {
                    int jc = jbase + nt * 8 + q;
                    float x0 = acc[nt][q];
                    float x1 = acc[nt][2 + q];
                    if (jc == p0) pos0 = x0;
                    if (jc == p1) pos1 = x1;
                    if (jc == rowG0)     x0 = -CUDART_INF_F;
                    if (jc == rowG0 + 8) x1 = -CUDART_INF_F;
                    a0 += exp2f(x0 - COFF);
                    a1 += exp2f(x1 - COFF);
                }
            }
            s0r += a0; s1r += a1;
        } else {
            float a0 = 0.f, a1 = 0.f;
            #pragma unroll
            for (int nt = 0; nt < 8; nt++) {
                a0 += exp2f(acc[nt][0] - COFF) + exp2f(acc[nt][1] - COFF);
                a1 += exp2f(acc[nt][2] - COFF) + exp2f(acc[nt][3] - COFF);
            }
            s0r += a0; s1r += a1;
        }
    }

    #pragma unroll
    for (int o = 1; o <= 2; o <<= 1) {
        s0r += __shfl_xor_sync(0xffffffffu, s0r, o);
        s1r += __shfl_xor_sync(0xffffffffu, s1r, o);
        pos0 = fmaxf(pos0, __shfl_xor_sync(0xffffffffu, pos0, o));
        pos1 = fmaxf(pos1, __shfl_xor_sync(0xffffffffu, pos1, o));
    }
    if (tig == 0) {
        int row = js * NTOT + rowBlock + r0 + g;
        g_ls[row] = s0r; g_lp[row] = pos0;
        g_ls[row + 8] = s1r; g_lp[row + 8] = pos1;
    }
}

__device__ __forceinline__ void graph_body(SmemU* sm, int gb,
                                           const float* __restrict__ G,
                                           const float* __restrict__ sub_x) {
    int tid = threadIdx.x;
    int warp = tid >> 5, lane = tid & 31;
    int g = lane >> 2, tig = lane & 3;
    int rb  = gb & 31;
    int ksp = gb >> 5;
    int rowBase = rb * 128;
    int kBase   = ksp * GKS;

    float acc[16][4];
    #pragma unroll
    for (int nt = 0; nt < 16; nt++)
        acc[nt][0] = acc[nt][1] = acc[nt][2] = acc[nt][3] = 0.f;
    float rsum0 = 0.f, rsum1 = 0.f, t2p = 0.f;

    int r0 = warp * 16;
    int rowA = rowBase + r0 + g;
    int rowB = rowA + 8;
    const float* gRowA = G + (size_t)rowA * KDIM + kBase + tig * 2;
    const float* gRowB = G + (size_t)rowB * KDIM + kBase + tig * 2;
    const float* axp   = g_ax2 + kBase + tig * 2;

    unsigned xsh[2];
    xsh[0] = (unsigned)__cvta_generic_to_shared(&sm->g.xs[0][0]);
    xsh[1] = (unsigned)__cvta_generic_to_shared(&sm->g.xs[1][0]);

    #pragma unroll
    for (int j = 0; j < 2; j++) {
        int i = tid + j * 256;
        int d = i >> 2, q = i & 3;
        cp16(xsh[0] + (d * KPX + q * 8) * 2, g_axT + d * KDIM + kBase + q * 8);
    }
    cp_commit();

    float2 bA0 = *reinterpret_cast<const float2*>(gRowA);
    float2 bB0 = *reinterpret_cast<const float2*>(gRowB);
    float2 bA1 = *reinterpret_cast<const float2*>(gRowA + 8);
    float2 bB1 = *reinterpret_cast<const float2*>(gRowB + 8);

    for (int kt = 0; kt < GKS / 32; kt++) {
        int cur = kt & 1;
        cp_wait<0>();
        __syncthreads();
        if (kt + 1 < GKS / 32) {
            #pragma unroll
            for (int j = 0; j < 2; j++) {
                int i = tid + j * 256;
                int d = i >> 2, q = i & 3;
                cp16(xsh[cur ^ 1] + (d * KPX + q * 8) * 2,
                     g_axT + d * KDIM + kBase + (kt + 1) * 32 + q * 8);
            }
            cp_commit();
        }

        #pragma unroll
        for (int ks = 0; ks < 2; ks++) {
            int kk = kt * 2 + ks;
            float2 vA0 = bA0, vB0 = bB0, vA1 = bA1, vB1 = bB1;
            int ncol = (kk + 1 < GKS / 16) ? (kk + 1) * 16 : 0;
            bA0 = *reinterpret_cast<const float2*>(gRowA + ncol);
            bB0 = *reinterpret_cast<const float2*>(gRowB + ncol);
            bA1 = *reinterpret_cast<const float2*>(gRowA + ncol + 8);
            bB1 = *reinterpret_cast<const float2*>(gRowB + ncol + 8);

            rsum0 += vA0.x + vA0.y + vA1.x + vA1.y;
            rsum1 += vB0.x + vB0.y + vB1.x + vB1.y;

            float2 w0 = *reinterpret_cast<const float2*>(axp + kk * 16);
            float2 w1 = *reinterpret_cast<const float2*>(axp + kk * 16 + 8);
            t2p += (vA0.x + vB0.x) * w0.x + (vA0.y + vB0.y) * w0.y
                 + (vA1.x + vB1.x) * w1.x + (vA1.y + vB1.y) * w1.y;

            unsigned af[4];
            af[0] = pack_bf2(vA0.x, vA0.y);
            af[1] = pack_bf2(vB0.x, vB0.y);
            af[2] = pack_bf2(vA1.x, vA1.y);
            af[3] = pack_bf2(vB1.x, vB1.y);
            #pragma unroll
            for (int nt = 0; nt < 16; nt++) {
                const __nv_bfloat16* bp = &sm->g.xs[cur][(nt * 8 + g) * KPX + ks * 16 + tig * 2];
                unsigned b0 = *reinterpret_cast<const unsigned*>(bp);
                unsigned b1 = *reinterpret_cast<const unsigned*>(bp + 8);
                mma_bf16(acc[nt], af, b0, b1);
            }
        }
    }

    float t3p = 0.f;
    #pragma unroll
    for (int nt = 0; nt < 16; nt++) {
        int d = nt * 8 + tig * 2;
        float2 s0 = *reinterpret_cast<const float2*>(sub_x + rowA * DDIM + d);
        float2 s1 = *reinterpret_cast<const float2*>(sub_x + rowB * DDIM + d);
        t3p += acc[nt][0] * s0.x + acc[nt][1] * s0.y + acc[nt][2] * s1.x + acc[nt][3] * s1.y;
    }
    #pragma unroll
    for (int o = 16; o; o >>= 1) t3p += __shfl_xor_sync(0xffffffffu, t3p, o);
    if (lane == 0) atomicAdd(&g_acc[2], t3p);

    #pragma unroll
    for (int o = 16; o; o >>= 1) t2p += __shfl_xor_sync(0xffffffffu, t2p, o);
    if (lane == 0) atomicAdd(&g_acc[3], t2p);

    rsum0 += __shfl_xor_sync(0xffffffffu, rsum0, 1);
    rsum0 += __shfl_xor_sync(0xffffffffu, rsum0, 2);
    rsum1 += __shfl_xor_sync(0xffffffffu, rsum1, 1);
    rsum1 += __shfl_xor_sync(0xffffffffu, rsum1, 2);
    float t1p = 0.f;
    if (tig == 0) t1p = rsum0 * g_xs2[rowA] + rsum1 * g_xs2[rowB];
    #pragma unroll
    for (int o = 4; o <= 16; o <<= 1) t1p += __shfl_xor_sync(0xffffffffu, t1p, o);
    if (lane == 0) atomicAdd(&g_acc[1], t1p);
}

__global__ void __launch_bounds__(256, 2) fused_kernel(const float* __restrict__ G,
                                                       const float* __restrict__ sub_x) {
    __shared__ SmemU sm;
    if (blockIdx.x & 1) graph_body(&sm, blockIdx.x >> 1, G, sub_x);
    else                contrastive_body(&sm, blockIdx.x >> 1);
}

// ---------------- finalize: parallel LSE reduce + last-block combine ----------------
__global__ void __launch_bounds__(256) finalize_kernel(float* __restrict__ out) {
    __shared__ float red[8];
    __shared__ bool isLast;
    int tid = threadIdx.x;
    int r = blockIdx.x * 256 + tid;          // 32 blocks x 256 = 8192 rows, 1 per thread

    float s = g_ls[r], p = g_lp[r];
    #pragma unroll
    for (int js = 1; js < NJS; js++) {
        s += g_ls[js * NTOT + r];
        p = fmaxf(p, g_lp[js * NTOT + r]);
    }
    float csum = LN2F * (COFF + log2f(s) - p);

    #pragma unroll
    for (int o = 16; o; o >>= 1) csum += __shfl_xor_sync(0xffffffffu, csum, o);
    if ((tid & 31) == 0) red[tid >> 5] = csum;
    __syncthreads();
    if (tid == 0) {
        float bs = 0.f;
        #pragma unroll
        for (int i = 0; i < 8; i++) bs += red[i];
        atomicAdd(&g_csum, bs);
        __threadfence();
        isLast = (atomicAdd(&g_ctr, 1u) == (unsigned)(gridDim.x - 1));
    }
    __syncthreads();
    if (isLast && tid == 0) {
        float cs = *((volatile float*)&g_csum);
        float contr = cs / (float)NTOT;
        float graph = (g_acc[1] + g_acc[3] - 2.0f * g_acc[2]) / ((float)BHALF * (float)KDIM);
        out[0] = contr + graph;
    }
}

// ---------------- launch ----------------
extern "C" void kernel_launch(void* const* d_in, const int* in_sizes, int n_in,
                              void* d_out, int out_size) {
    (void)in_sizes; (void)n_in; (void)out_size;
    const float* h_i   = (const float*)d_in[0];
    const float* h_j   = (const float*)d_in[1];
    const float* G     = (const float*)d_in[2];
    const float* sub_x = (const float*)d_in[3];
    const float* all_x = (const float*)d_in[4];
    float* out = (float*)d_out;

    prep_kernel<<<1536, 256>>>(h_i, h_j, sub_x, all_x);
    fused_kernel<<<512, 256>>>(G, sub_x);
    finalize_kernel<<<32, 256>>>(out);
}